// round 5
// baseline (speedup 1.0000x reference)
#include <cuda_runtime.h>
#include <cstdint>

#define T_DIM 2048
#define B_DIM 256
#define D_DIM 256
#define H_DIM 8
#define G_DIM 32
#define M_DIM (T_DIM * B_DIM)

// Scratch for x_gates (+ folded biases): [T, B, 32] fp32 = 64 MB
__device__ float g_xg[(size_t)M_DIM * G_DIM];

// ---------------------------------------------------------------------------
// Packed f32x2 FMA (sm_103a): d = a*b + d  (two independent fp32 FMAs)
// ---------------------------------------------------------------------------
__device__ __forceinline__ void fma2(unsigned long long& d,
                                     unsigned long long a,
                                     unsigned long long b) {
    asm("fma.rn.f32x2 %0, %1, %2, %0;" : "+l"(d) : "l"(a), "l"(b));
}

__device__ __forceinline__ float ex2a(float x) {
    float y; asm("ex2.approx.ftz.f32 %0, %1;" : "=f"(y) : "f"(x)); return y;
}
__device__ __forceinline__ float rcpa(float x) {
    float y; asm("rcp.approx.ftz.f32 %0, %1;" : "=f"(y) : "f"(x)); return y;
}

// ---------------------------------------------------------------------------
// GEMM v2: x_gates[m, g] = sum_k x[m,k] * W_ih[g,k] + (b_ih[g] + b_hh[g])
// M = 524288, K = 256, N = 32.  f32x2 packs k-pairs.
// Block: 256 threads, 64-row tile, 2 CTAs/SM -> 4 warps/SMSP (2x R4's
// latency hiding). Thread tile: 2 rows x 4 gates (g0, g0+8, g0+16, g0+24).
// Per warp x-LDS is 8-way broadcast (4 distinct addrs), w-LDS 4-way (8).
// ---------------------------------------------------------------------------
#define GROWS 64
#define SX 258
#define SW 33
#define GEMM_SMEM (GROWS * SX * 4 + 128 * SW * 8)

__global__ void __launch_bounds__(256, 2) gemm_k(
    const float* __restrict__ x, const float* __restrict__ W_ih,
    const float* __restrict__ b_ih, const float* __restrict__ b_hh)
{
    extern __shared__ float sm[];
    float* xs = sm;                                                  // [64][SX]
    unsigned long long* ws = (unsigned long long*)(sm + GROWS * SX); // [128][SW]
    const int tid = threadIdx.x;
    const size_t row0 = (size_t)blockIdx.x * GROWS;

    // Stage W: W_ih[g][2kp..2kp+1] -> ws[kp*SW + g] (k-pair packed)
    const float2* W2 = (const float2*)W_ih;
    for (int u = tid; u < 32 * 128; u += 256) {
        int g = u >> 7, kp = u & 127;
        float2 v = W2[(size_t)g * 128 + kp];
        ((float2*)ws)[kp * SW + g] = v;
    }
    // Stage x tile (coalesced float4 loads, float2 smem stores)
    const float4* X4 = (const float4*)(x + row0 * D_DIM);
    for (int u = tid; u < GROWS * 64; u += 256) {
        int r = u >> 6, k4 = u & 63;
        float4 v = X4[(size_t)r * 64 + k4];
        float2* dst = (float2*)&xs[r * SX + k4 * 4];
        dst[0] = make_float2(v.x, v.y);
        dst[1] = make_float2(v.z, v.w);
    }
    __syncthreads();

    const int g0 = tid & 7;
    const int rb = (tid >> 3) * 2;   // 32 row-groups x 2 rows = 64 rows

    unsigned long long acc[2][4];
#pragma unroll
    for (int i = 0; i < 2; i++)
#pragma unroll
        for (int j = 0; j < 4; j++) acc[i][j] = 0ULL;

    const unsigned long long* xr0 = (const unsigned long long*)&xs[(rb + 0) * SX];
    const unsigned long long* xr1 = (const unsigned long long*)&xs[(rb + 1) * SX];

#pragma unroll 8
    for (int kp = 0; kp < 128; kp++) {
        unsigned long long w0 = ws[kp * SW + g0 + 0];
        unsigned long long w1 = ws[kp * SW + g0 + 8];
        unsigned long long w2 = ws[kp * SW + g0 + 16];
        unsigned long long w3 = ws[kp * SW + g0 + 24];
        unsigned long long xa = xr0[kp], xb = xr1[kp];
        fma2(acc[0][0], xa, w0); fma2(acc[0][1], xa, w1);
        fma2(acc[0][2], xa, w2); fma2(acc[0][3], xa, w3);
        fma2(acc[1][0], xb, w0); fma2(acc[1][1], xb, w1);
        fma2(acc[1][2], xb, w2); fma2(acc[1][3], xb, w3);
    }

    float bias[4];
#pragma unroll
    for (int j = 0; j < 4; j++) bias[j] = b_ih[g0 + 8 * j] + b_hh[g0 + 8 * j];
#pragma unroll
    for (int i = 0; i < 2; i++) {
#pragma unroll
        for (int j = 0; j < 4; j++) {
            unsigned lo = (unsigned)acc[i][j];
            unsigned hi = (unsigned)(acc[i][j] >> 32);
            float s = __uint_as_float(lo) + __uint_as_float(hi) + bias[j];
            g_xg[(row0 + rb + i) * G_DIM + g0 + 8 * j] = s;
        }
    }
}

// ---------------------------------------------------------------------------
// Segment-parallel LSTM scan (unchanged from R4 — 176us, known correct).
// reset==1 at (t,b) zeroes h,c BEFORE step t, so every reset begins an
// independent segment with h0=c0=0. One warp per (t,b): the warp exits
// unless (t==0 || reset[t,b]==1); otherwise it runs its whole segment.
// ---------------------------------------------------------------------------
__global__ void __launch_bounds__(256) scan_seg_k(
    const int* __restrict__ reset,
    const float* __restrict__ W_hh, const float* __restrict__ W_proj,
    const float* __restrict__ b_proj, float* __restrict__ out)
{
    const int lane = threadIdx.x & 31;
    const int wid = (blockIdx.x * blockDim.x + threadIdx.x) >> 5;
    const int t0 = wid >> 8;    // time index  (T_DIM = 2048)
    const int b  = wid & 255;   // batch index (B_DIM = 256)

    // Segment-start check (warp-uniform): broadcast load of one int.
    const int rstart = reset[(size_t)t0 * B_DIM + b];
    if (t0 != 0 && rstart == 0) return;

    float w[8], wp[8];
#pragma unroll
    for (int j = 0; j < 8; j++) w[j] = W_hh[lane * 8 + j];
#pragma unroll
    for (int j = 0; j < 8; j++) wp[j] = W_proj[j];
    const float bp = b_proj[0];

    // sigmoid lanes: i (0-7), f (8-15), o (24-31); tanh lanes: g (16-23)
    const bool sg = (lane < 16) || (lane >= 24);
    const float EB = sg ? -1.4426950408889634f : -2.8853900817779268f;
    const float AA = sg ? 1.0f : 2.0f;
    const float CC = sg ? 0.0f : -1.0f;

    float h[8];
#pragma unroll
    for (int j = 0; j < 8; j++) h[j] = 0.f;
    float cc = 0.f;

    const float* xp = g_xg + (size_t)b * G_DIM + lane;
    float xcur = xp[(size_t)t0 * (B_DIM * G_DIM)];

    int base = t0;
    while (true) {
        // Window of resets for steps base .. base+31 (bit0 = base itself,
        // masked off: segment-start reset must not terminate its own segment,
        // and mid-segment window heads are known-zero).
        const int idx = base + lane;
        const int rw = (idx < T_DIM) ? reset[(size_t)idx * B_DIM + b] : 1;
        unsigned m = __ballot_sync(0xffffffffu, rw != 0) & 0xfffffffeu;
        const int cnt = m ? (__ffs((int)m) - 1) : 32;  // steps in this window

        for (int i = 0; i < cnt; i++) {
            const int tt = base + i;
            // prefetch next step's x_gates (harmless past segment end)
            float xnext = 0.f;
            if (tt + 1 < T_DIM) xnext = xp[(size_t)(tt + 1) * (B_DIM * G_DIM)];

            // gate pre-activation: xg + W_hh[lane,:] . h   (keep == 1)
            float d0 = fmaf(w[1], h[1], w[0] * h[0]);
            d0 = fmaf(w[2], h[2], d0);
            d0 = fmaf(w[3], h[3], d0);
            float d1 = fmaf(w[5], h[5], w[4] * h[4]);
            d1 = fmaf(w[6], h[6], d1);
            d1 = fmaf(w[7], h[7], d1);
            const float gate = xcur + (d0 + d1);
            // act = AA * 1/(1 + 2^(EB*gate)) + CC   (sigmoid or tanh)
            const float act = fmaf(AA, rcpa(1.0f + ex2a(EB * gate)), CC);
            // gather i,f,g,o for this lane's h-index
            const float iv = __shfl_sync(0xffffffffu, act, (lane & 7));
            const float fv = __shfl_sync(0xffffffffu, act, (lane & 7) + 8);
            const float gv = __shfl_sync(0xffffffffu, act, (lane & 7) + 16);
            const float ov = __shfl_sync(0xffffffffu, act, (lane & 7) + 24);
            const float cn = fmaf(fv, cc, iv * gv);
            const float tc = fmaf(2.0f,
                rcpa(1.0f + ex2a(-2.8853900817779268f * cn)), -1.0f);
            const float hv = ov * tc;   // lane L holds h_{L&7}
            cc = cn;
#pragma unroll
            for (int j = 0; j < 8; j++) h[j] = __shfl_sync(0xffffffffu, hv, j);
            // projection
            float pv = bp;
#pragma unroll
            for (int j = 0; j < 8; j++) pv = fmaf(h[j], wp[j], pv);
            if (lane == 0) out[(size_t)tt * B_DIM + b] = pv;
            xcur = xnext;
        }

        if (cnt < 32) return;   // next reset (or T end) terminates segment
        base += 32;             // rare: segment longer than window
    }
}

// ---------------------------------------------------------------------------
extern "C" void kernel_launch(void* const* d_in, const int* in_sizes, int n_in,
                              void* d_out, int out_size)
{
    const float* x      = (const float*)d_in[0];
    const int*   reset  = (const int*)d_in[1];
    const float* W_ih   = (const float*)d_in[2];
    const float* W_hh   = (const float*)d_in[3];
    const float* b_ih   = (const float*)d_in[4];
    const float* b_hh   = (const float*)d_in[5];
    const float* W_proj = (const float*)d_in[6];
    const float* b_proj = (const float*)d_in[7];
    float* out = (float*)d_out;

    (void)in_sizes; (void)n_in; (void)out_size;

    cudaFuncSetAttribute(gemm_k, cudaFuncAttributeMaxDynamicSharedMemorySize,
                         GEMM_SMEM);
    gemm_k<<<M_DIM / GROWS, 256, GEMM_SMEM>>>(x, W_ih, b_ih, b_hh);
    // one warp per (t, b): T*B warps, 8 warps (256 threads) per block
    scan_seg_k<<<(M_DIM * 32) / 256, 256>>>(reset, W_hh, W_proj, b_proj, out);
}

// round 12
// speedup vs baseline: 1.2407x; 1.2407x over previous
#include <cuda_runtime.h>
#include <cstdint>

#define T_DIM 2048
#define B_DIM 256
#define D_DIM 256
#define H_DIM 8
#define G_DIM 32
#define M_DIM (T_DIM * B_DIM)

// Scratch for x_gates (+ folded biases): [T, B, 32] fp32 = 64 MB
__device__ float g_xg[(size_t)M_DIM * G_DIM];

// ---------------------------------------------------------------------------
// Packed f32x2 FMA (sm_103a): d = a*b + d  (two independent fp32 FMAs)
// ---------------------------------------------------------------------------
__device__ __forceinline__ void fma2(unsigned long long& d,
                                     unsigned long long a,
                                     unsigned long long b) {
    asm("fma.rn.f32x2 %0, %1, %2, %0;" : "+l"(d) : "l"(a), "l"(b));
}

__device__ __forceinline__ float ex2a(float x) {
    float y; asm("ex2.approx.ftz.f32 %0, %1;" : "=f"(y) : "f"(x)); return y;
}
__device__ __forceinline__ float rcpa(float x) {
    float y; asm("rcp.approx.ftz.f32 %0, %1;" : "=f"(y) : "f"(x)); return y;
}

// ---------------------------------------------------------------------------
// GEMM v3c: x_gates[m, g] = sum_k x[m,k] * W_ih[g,k] + (b_ih[g] + b_hh[g])
// M = 524288, K = 256, N = 32.
// Block: 128 threads, 64-row tile, 2 CTAs/SM. Thread tile: 4 rows x 4 gates,
// 4 k per inner iter => per iter: 8x LDS.128 + 32x FFMA2 (0.25 LDS/FFMA2).
// BUGFIX vs v3/v3b: x row stride 268 (was 260). The +8-float shift on odd
// 8-row blocks makes a shifted row's footprint 264 floats; stride 260 made
// adjacent shifted rows OVERLAP by 4 floats (the rel_err 5.4e-2 in R6/R10).
// 268 >= 264: disjoint. Banks: quad(r) = r*67 mod 8 = {0,4,0,4} over a
// warp's 4 rows, +2 quads on shifted blocks -> {0,4,2,6}: conflict-free.
// W repacked [kp2][gate] float4-width (stride 132): quads g0 = 0..7: free.
// ---------------------------------------------------------------------------
#define GROWS 64
#define SXF 268                      // x row stride in floats (>= 264!)
#define XS_FLOATS (GROWS * SXF + 8)  // + swizzle shift headroom
#define SW2 132                      // w row stride in floats
#define WS_FLOATS (64 * SW2)
#define GEMM_SMEM ((XS_FLOATS + WS_FLOATS) * 4)

__device__ __forceinline__ int xrow_off(int r) {
    return r * SXF + ((r >> 3) & 1) * 8;
}

__global__ void __launch_bounds__(128, 2) gemm_k(
    const float* __restrict__ x, const float* __restrict__ W_ih,
    const float* __restrict__ b_ih, const float* __restrict__ b_hh)
{
    extern __shared__ float sm[];
    float* xs = sm;                       // swizzled [64 rows]
    float* ws = sm + XS_FLOATS;           // [64 kp2][32 gates] float4-width
    const int tid = threadIdx.x;
    const size_t row0 = (size_t)blockIdx.x * GROWS;

    // Stage W: ws[kp2*132 + g*4 .. +3] = W_ih[g][4*kp2 .. 4*kp2+3]
    const float4* W4 = (const float4*)W_ih;   // W row = 64 float4
    for (int u = tid; u < 64 * 32; u += 128) {
        int kp2 = u >> 5, g = u & 31;
        float4 v = W4[(size_t)g * 64 + kp2];
        *(float4*)&ws[kp2 * SW2 + g * 4] = v;
    }
    // Stage x tile (coalesced float4 loads, float4 smem stores)
    const float4* X4 = (const float4*)(x + row0 * D_DIM);
    for (int u = tid; u < GROWS * 64; u += 128) {
        int r = u >> 6, k4 = u & 63;
        float4 v = X4[(size_t)r * 64 + k4];
        *(float4*)&xs[xrow_off(r) + k4 * 4] = v;
    }
    __syncthreads();

    const int g0 = tid & 7;
    const int rb = (tid >> 3) * 4;

    unsigned long long acc[4][4];
#pragma unroll
    for (int i = 0; i < 4; i++)
#pragma unroll
        for (int j = 0; j < 4; j++) acc[i][j] = 0ULL;

    const float* xr0 = &xs[xrow_off(rb + 0)];
    const float* xr1 = &xs[xrow_off(rb + 1)];
    const float* xr2 = &xs[xrow_off(rb + 2)];
    const float* xr3 = &xs[xrow_off(rb + 3)];
    const float* wb0 = &ws[(g0 + 0) * 4];
    const float* wb1 = &ws[(g0 + 8) * 4];
    const float* wb2 = &ws[(g0 + 16) * 4];
    const float* wb3 = &ws[(g0 + 24) * 4];

#pragma unroll 4
    for (int kp2 = 0; kp2 < 64; kp2++) {
        const ulonglong2 w0 = *(const ulonglong2*)(wb0 + kp2 * SW2);
        const ulonglong2 w1 = *(const ulonglong2*)(wb1 + kp2 * SW2);
        const ulonglong2 w2 = *(const ulonglong2*)(wb2 + kp2 * SW2);
        const ulonglong2 w3 = *(const ulonglong2*)(wb3 + kp2 * SW2);
        const ulonglong2 xa = *(const ulonglong2*)(xr0 + kp2 * 4);
        const ulonglong2 xb = *(const ulonglong2*)(xr1 + kp2 * 4);
        const ulonglong2 xc = *(const ulonglong2*)(xr2 + kp2 * 4);
        const ulonglong2 xd = *(const ulonglong2*)(xr3 + kp2 * 4);

        fma2(acc[0][0], xa.x, w0.x); fma2(acc[0][1], xa.x, w1.x);
        fma2(acc[0][2], xa.x, w2.x); fma2(acc[0][3], xa.x, w3.x);
        fma2(acc[0][0], xa.y, w0.y); fma2(acc[0][1], xa.y, w1.y);
        fma2(acc[0][2], xa.y, w2.y); fma2(acc[0][3], xa.y, w3.y);

        fma2(acc[1][0], xb.x, w0.x); fma2(acc[1][1], xb.x, w1.x);
        fma2(acc[1][2], xb.x, w2.x); fma2(acc[1][3], xb.x, w3.x);
        fma2(acc[1][0], xb.y, w0.y); fma2(acc[1][1], xb.y, w1.y);
        fma2(acc[1][2], xb.y, w2.y); fma2(acc[1][3], xb.y, w3.y);

        fma2(acc[2][0], xc.x, w0.x); fma2(acc[2][1], xc.x, w1.x);
        fma2(acc[2][2], xc.x, w2.x); fma2(acc[2][3], xc.x, w3.x);
        fma2(acc[2][0], xc.y, w0.y); fma2(acc[2][1], xc.y, w1.y);
        fma2(acc[2][2], xc.y, w2.y); fma2(acc[2][3], xc.y, w3.y);

        fma2(acc[3][0], xd.x, w0.x); fma2(acc[3][1], xd.x, w1.x);
        fma2(acc[3][2], xd.x, w2.x); fma2(acc[3][3], xd.x, w3.x);
        fma2(acc[3][0], xd.y, w0.y); fma2(acc[3][1], xd.y, w1.y);
        fma2(acc[3][2], xd.y, w2.y); fma2(acc[3][3], xd.y, w3.y);
    }

    float bias[4];
#pragma unroll
    for (int j = 0; j < 4; j++) bias[j] = b_ih[g0 + 8 * j] + b_hh[g0 + 8 * j];
#pragma unroll
    for (int i = 0; i < 4; i++) {
#pragma unroll
        for (int j = 0; j < 4; j++) {
            unsigned lo = (unsigned)acc[i][j];
            unsigned hi = (unsigned)(acc[i][j] >> 32);
            float s = __uint_as_float(lo) + __uint_as_float(hi) + bias[j];
            g_xg[(row0 + rb + i) * G_DIM + g0 + 8 * j] = s;
        }
    }
}

// ---------------------------------------------------------------------------
// Segment-parallel LSTM scan (unchanged from R4 — 176us, known correct).
// reset==1 at (t,b) zeroes h,c BEFORE step t, so every reset begins an
// independent segment with h0=c0=0. One warp per (t,b): the warp exits
// unless (t==0 || reset[t,b]==1); otherwise it runs its whole segment.
// ---------------------------------------------------------------------------
__global__ void __launch_bounds__(256) scan_seg_k(
    const int* __restrict__ reset,
    const float* __restrict__ W_hh, const float* __restrict__ W_proj,
    const float* __restrict__ b_proj, float* __restrict__ out)
{
    const int lane = threadIdx.x & 31;
    const int wid = (blockIdx.x * blockDim.x + threadIdx.x) >> 5;
    const int t0 = wid >> 8;    // time index  (T_DIM = 2048)
    const int b  = wid & 255;   // batch index (B_DIM = 256)

    const int rstart = reset[(size_t)t0 * B_DIM + b];
    if (t0 != 0 && rstart == 0) return;

    float w[8], wp[8];
#pragma unroll
    for (int j = 0; j < 8; j++) w[j] = W_hh[lane * 8 + j];
#pragma unroll
    for (int j = 0; j < 8; j++) wp[j] = W_proj[j];
    const float bp = b_proj[0];

    // sigmoid lanes: i (0-7), f (8-15), o (24-31); tanh lanes: g (16-23)
    const bool sg = (lane < 16) || (lane >= 24);
    const float EB = sg ? -1.4426950408889634f : -2.8853900817779268f;
    const float AA = sg ? 1.0f : 2.0f;
    const float CC = sg ? 0.0f : -1.0f;

    float h[8];
#pragma unroll
    for (int j = 0; j < 8; j++) h[j] = 0.f;
    float cc = 0.f;

    const float* xp = g_xg + (size_t)b * G_DIM + lane;
    float xcur = xp[(size_t)t0 * (B_DIM * G_DIM)];

    int base = t0;
    while (true) {
        const int idx = base + lane;
        const int rw = (idx < T_DIM) ? reset[(size_t)idx * B_DIM + b] : 1;
        unsigned m = __ballot_sync(0xffffffffu, rw != 0) & 0xfffffffeu;
        const int cnt = m ? (__ffs((int)m) - 1) : 32;  // steps in this window

        for (int i = 0; i < cnt; i++) {
            const int tt = base + i;
            float xnext = 0.f;
            if (tt + 1 < T_DIM) xnext = xp[(size_t)(tt + 1) * (B_DIM * G_DIM)];

            float d0 = fmaf(w[1], h[1], w[0] * h[0]);
            d0 = fmaf(w[2], h[2], d0);
            d0 = fmaf(w[3], h[3], d0);
            float d1 = fmaf(w[5], h[5], w[4] * h[4]);
            d1 = fmaf(w[6], h[6], d1);
            d1 = fmaf(w[7], h[7], d1);
            const float gate = xcur + (d0 + d1);
            const float act = fmaf(AA, rcpa(1.0f + ex2a(EB * gate)), CC);
            const float iv = __shfl_sync(0xffffffffu, act, (lane & 7));
            const float fv = __shfl_sync(0xffffffffu, act, (lane & 7) + 8);
            const float gv = __shfl_sync(0xffffffffu, act, (lane & 7) + 16);
            const float ov = __shfl_sync(0xffffffffu, act, (lane & 7) + 24);
            const float cn = fmaf(fv, cc, iv * gv);
            const float tc = fmaf(2.0f,
                rcpa(1.0f + ex2a(-2.8853900817779268f * cn)), -1.0f);
            const float hv = ov * tc;   // lane L holds h_{L&7}
            cc = cn;
#pragma unroll
            for (int j = 0; j < 8; j++) h[j] = __shfl_sync(0xffffffffu, hv, j);
            float pv = bp;
#pragma unroll
            for (int j = 0; j < 8; j++) pv = fmaf(h[j], wp[j], pv);
            if (lane == 0) out[(size_t)tt * B_DIM + b] = pv;
            xcur = xnext;
        }

        if (cnt < 32) return;   // next reset (or T end) terminates segment
        base += 32;             // rare: segment longer than window
    }
}

// ---------------------------------------------------------------------------
extern "C" void kernel_launch(void* const* d_in, const int* in_sizes, int n_in,
                              void* d_out, int out_size)
{
    const float* x      = (const float*)d_in[0];
    const int*   reset  = (const int*)d_in[1];
    const float* W_ih   = (const float*)d_in[2];
    const float* W_hh   = (const float*)d_in[3];
    const float* b_ih   = (const float*)d_in[4];
    const float* b_hh   = (const float*)d_in[5];
    const float* W_proj = (const float*)d_in[6];
    const float* b_proj = (const float*)d_in[7];
    float* out = (float*)d_out;

    (void)in_sizes; (void)n_in; (void)out_size;

    cudaFuncSetAttribute(gemm_k, cudaFuncAttributeMaxDynamicSharedMemorySize,
                         GEMM_SMEM);
    gemm_k<<<M_DIM / GROWS, 128, GEMM_SMEM>>>(x, W_ih, b_ih, b_hh);
    // one warp per (t, b): T*B warps, 8 warps (256 threads) per block
    scan_seg_k<<<(M_DIM * 32) / 256, 256>>>(reset, W_hh, W_proj, b_proj, out);
}

// round 14
// speedup vs baseline: 1.5221x; 1.2267x over previous
#include <cuda_runtime.h>
#include <cstdint>

#define T_DIM 2048
#define B_DIM 256
#define D_DIM 256
#define H_DIM 8
#define G_DIM 32
#define M_DIM (T_DIM * B_DIM)

// Scratch for x_gates (+ folded biases): [T*B][8 h-idx][4 gates i,f,g,o] fp32
__device__ float g_xg[(size_t)M_DIM * G_DIM];

// ---------------------------------------------------------------------------
// Packed f32x2 FMA (sm_103a): d = a*b + d  (two independent fp32 FMAs)
// ---------------------------------------------------------------------------
__device__ __forceinline__ void fma2(unsigned long long& d,
                                     unsigned long long a,
                                     unsigned long long b) {
    asm("fma.rn.f32x2 %0, %1, %2, %0;" : "+l"(d) : "l"(a), "l"(b));
}

__device__ __forceinline__ float ex2a(float x) {
    float y; asm("ex2.approx.ftz.f32 %0, %1;" : "=f"(y) : "f"(x)); return y;
}
__device__ __forceinline__ float rcpa(float x) {
    float y; asm("rcp.approx.ftz.f32 %0, %1;" : "=f"(y) : "f"(x)); return y;
}

// ---------------------------------------------------------------------------
// GEMM (v1, identical to R4's known-330us kernel except the epilogue store
// layout): x_gates[m, g] = sum_k x[m,k] * W_ih[g,k] + (b_ih[g] + b_hh[g])
// M = 524288, K = 256, N = 32.  f32x2 packs k-pairs.
// Block: 128 threads, 64-row tile, full K staged in smem, 2 CTAs/SM.
// Thread: 4 rows x 4 gates (g0, g0+8, g0+16, g0+24; g0 = tid&7).
// NEW epilogue layout: [row][h_idx g0][gate-block j] so the scan reads one
// float4 {i,f,g,o} per h-index.
// ---------------------------------------------------------------------------
#define GROWS 64
#define SX 258
#define SW 33
#define GEMM_SMEM (GROWS * SX * 4 + 128 * SW * 8)

__global__ void __launch_bounds__(128, 2) gemm_k(
    const float* __restrict__ x, const float* __restrict__ W_ih,
    const float* __restrict__ b_ih, const float* __restrict__ b_hh)
{
    extern __shared__ float sm[];
    float* xs = sm;                                                  // [64][SX]
    unsigned long long* ws = (unsigned long long*)(sm + GROWS * SX); // [128][SW]
    const int tid = threadIdx.x;
    const size_t row0 = (size_t)blockIdx.x * GROWS;

    const float2* W2 = (const float2*)W_ih;
    for (int u = tid; u < 32 * 128; u += 128) {
        int g = u >> 7, kp = u & 127;
        float2 v = W2[(size_t)g * 128 + kp];
        ((float2*)ws)[kp * SW + g] = v;
    }
    const float4* X4 = (const float4*)(x + row0 * D_DIM);
    for (int u = tid; u < GROWS * 64; u += 128) {
        int r = u >> 6, k4 = u & 63;
        float4 v = X4[(size_t)r * 64 + k4];
        float2* dst = (float2*)&xs[r * SX + k4 * 4];
        dst[0] = make_float2(v.x, v.y);
        dst[1] = make_float2(v.z, v.w);
    }
    __syncthreads();

    const int g0 = tid & 7;
    const int rb = (tid >> 3) * 4;

    unsigned long long acc[4][4];
#pragma unroll
    for (int i = 0; i < 4; i++)
#pragma unroll
        for (int j = 0; j < 4; j++) acc[i][j] = 0ULL;

    const unsigned long long* xr0 = (const unsigned long long*)&xs[(rb + 0) * SX];
    const unsigned long long* xr1 = (const unsigned long long*)&xs[(rb + 1) * SX];
    const unsigned long long* xr2 = (const unsigned long long*)&xs[(rb + 2) * SX];
    const unsigned long long* xr3 = (const unsigned long long*)&xs[(rb + 3) * SX];

#pragma unroll 4
    for (int kp = 0; kp < 128; kp++) {
        unsigned long long w0 = ws[kp * SW + g0 + 0];
        unsigned long long w1 = ws[kp * SW + g0 + 8];
        unsigned long long w2 = ws[kp * SW + g0 + 16];
        unsigned long long w3 = ws[kp * SW + g0 + 24];
        unsigned long long xa = xr0[kp], xb = xr1[kp], xc = xr2[kp], xd = xr3[kp];
        fma2(acc[0][0], xa, w0); fma2(acc[0][1], xa, w1);
        fma2(acc[0][2], xa, w2); fma2(acc[0][3], xa, w3);
        fma2(acc[1][0], xb, w0); fma2(acc[1][1], xb, w1);
        fma2(acc[1][2], xb, w2); fma2(acc[1][3], xb, w3);
        fma2(acc[2][0], xc, w0); fma2(acc[2][1], xc, w1);
        fma2(acc[2][2], xc, w2); fma2(acc[2][3], xc, w3);
        fma2(acc[3][0], xd, w0); fma2(acc[3][1], xd, w1);
        fma2(acc[3][2], xd, w2); fma2(acc[3][3], xd, w3);
    }

    float bias[4];
#pragma unroll
    for (int j = 0; j < 4; j++) bias[j] = b_ih[g0 + 8 * j] + b_hh[g0 + 8 * j];
#pragma unroll
    for (int i = 0; i < 4; i++) {
#pragma unroll
        for (int j = 0; j < 4; j++) {
            unsigned lo = (unsigned)acc[i][j];
            unsigned hi = (unsigned)(acc[i][j] >> 32);
            float s = __uint_as_float(lo) + __uint_as_float(hi) + bias[j];
            // layout: [row][h_idx][i,f,g,o]
            g_xg[(row0 + rb + i) * G_DIM + g0 * 4 + j] = s;
        }
    }
}

// ---------------------------------------------------------------------------
// Segment-parallel LSTM scan v2: 8 lanes per (t,b) element, 4 elements/warp.
// Lane j of a group owns h_j and computes its 4 gates (W_hh rows j, j+8,
// j+16, j+24 in registers): no gather shuffles; only an 8-wide h broadcast.
// Group alive iff (t0==0 || reset[t0,b]==1); runs segment until next reset.
// Window-of-8 reset lookahead via ballot; bit 0 masked ONLY on the first
// window (it is the segment's own starting reset). On reload windows bit 0
// is live — this also makes idx >= T act as a terminating reset.
// ---------------------------------------------------------------------------
__global__ void __launch_bounds__(256) scan_seg4_k(
    const int* __restrict__ reset,
    const float* __restrict__ W_hh, const float* __restrict__ W_proj,
    const float* __restrict__ b_proj, float* __restrict__ out)
{
    const int lane = threadIdx.x & 31;
    const int wid = (blockIdx.x * blockDim.x + threadIdx.x) >> 5;
    const int grp = lane >> 3;            // 0..3: element slot in warp
    const int p   = lane & 7;             // h-index / window position
    const int gid = wid * 4 + grp;        // flat (t,b) id, < T*B
    const int t0 = gid >> 8;
    const int b  = gid & 255;

    bool alive = (t0 == 0) || (reset[(size_t)t0 * B_DIM + b] != 0);
    if (__ballot_sync(0xffffffffu, alive) == 0) return;

    // W_hh rows p (i), p+8 (f), p+16 (g), p+24 (o); each row = 2 float4
    float wi[8], wf[8], wg[8], wo[8], wp[8];
    const float4* W4 = (const float4*)W_hh;
    {
        float4 a, q;
        a = W4[(p +  0) * 2]; q = W4[(p +  0) * 2 + 1];
        wi[0]=a.x; wi[1]=a.y; wi[2]=a.z; wi[3]=a.w;
        wi[4]=q.x; wi[5]=q.y; wi[6]=q.z; wi[7]=q.w;
        a = W4[(p +  8) * 2]; q = W4[(p +  8) * 2 + 1];
        wf[0]=a.x; wf[1]=a.y; wf[2]=a.z; wf[3]=a.w;
        wf[4]=q.x; wf[5]=q.y; wf[6]=q.z; wf[7]=q.w;
        a = W4[(p + 16) * 2]; q = W4[(p + 16) * 2 + 1];
        wg[0]=a.x; wg[1]=a.y; wg[2]=a.z; wg[3]=a.w;
        wg[4]=q.x; wg[5]=q.y; wg[6]=q.z; wg[7]=q.w;
        a = W4[(p + 24) * 2]; q = W4[(p + 24) * 2 + 1];
        wo[0]=a.x; wo[1]=a.y; wo[2]=a.z; wo[3]=a.w;
        wo[4]=q.x; wo[5]=q.y; wo[6]=q.z; wo[7]=q.w;
    }
#pragma unroll
    for (int j = 0; j < 8; j++) wp[j] = W_proj[j];
    const float bp = b_proj[0];

    float h[8];
#pragma unroll
    for (int j = 0; j < 8; j++) h[j] = 0.f;
    float c = 0.f;

    const float4* xg4 = (const float4*)g_xg;   // [(t*256+b)*8 + h_idx]
    float4 xcur = xg4[((size_t)t0 * B_DIM + b) * 8 + p];

    int base = t0;
    while (true) {
        // reset window for steps base .. base+7
        const int idx = base + p;
        const int rw = (alive && idx < T_DIM)
                     ? reset[(size_t)idx * B_DIM + b] : 1;
        unsigned bal = __ballot_sync(0xffffffffu, rw != 0);
        unsigned m8 = (bal >> (grp * 8)) & 0xffu;
        if (base == t0) m8 &= 0xfeu;     // own starting reset doesn't end us
        int cnt = m8 ? (__ffs((int)m8) - 1) : 8;
        if (!alive) cnt = 0;

        for (int i = 0; i < 8; i++) {
            const bool stepping = alive && (i < cnt);
            if (__ballot_sync(0xffffffffu, stepping) == 0u) break;
            const int tt = base + i;
            // prefetch next x (off the critical chain); also feeds the first
            // step of the next window when i == 7
            float4 xnext = xcur;
            if (stepping && tt + 1 < T_DIM)
                xnext = xg4[((size_t)(tt + 1) * B_DIM + b) * 8 + p];

            float ig = xcur.x, fg = xcur.y, gg = xcur.z, og = xcur.w;
#pragma unroll
            for (int k = 0; k < 8; k++) {
                ig = fmaf(wi[k], h[k], ig);
                fg = fmaf(wf[k], h[k], fg);
                gg = fmaf(wg[k], h[k], gg);
                og = fmaf(wo[k], h[k], og);
            }
            const float iv = rcpa(1.f + ex2a(-1.4426950408889634f * ig));
            const float fv = rcpa(1.f + ex2a(-1.4426950408889634f * fg));
            const float gv = fmaf(2.f,
                rcpa(1.f + ex2a(-2.8853900817779268f * gg)), -1.f);
            const float ov = rcpa(1.f + ex2a(-1.4426950408889634f * og));
            const float cn = fmaf(fv, c, iv * gv);
            const float tc = fmaf(2.f,
                rcpa(1.f + ex2a(-2.8853900817779268f * cn)), -1.f);
            const float hj = ov * tc;
            if (stepping) c = cn;
            const float hsrc = stepping ? hj : h[p];  // keep old h if idle
#pragma unroll
            for (int k = 0; k < 8; k++)
                h[k] = __shfl_sync(0xffffffffu, hsrc, (lane & 24) + k);
            float pv = bp;
#pragma unroll
            for (int k = 0; k < 8; k++) pv = fmaf(h[k], wp[k], pv);
            if (stepping && p == 0) out[(size_t)tt * B_DIM + b] = pv;
            xcur = xnext;   // after i==7 this is x[base+8] for the next window
        }

        alive = alive && (cnt == 8);
        if (__ballot_sync(0xffffffffu, alive) == 0u) return;
        base += 8;
    }
}

// ---------------------------------------------------------------------------
extern "C" void kernel_launch(void* const* d_in, const int* in_sizes, int n_in,
                              void* d_out, int out_size)
{
    const float* x      = (const float*)d_in[0];
    const int*   reset  = (const int*)d_in[1];
    const float* W_ih   = (const float*)d_in[2];
    const float* W_hh   = (const float*)d_in[3];
    const float* b_ih   = (const float*)d_in[4];
    const float* b_hh   = (const float*)d_in[5];
    const float* W_proj = (const float*)d_in[6];
    const float* b_proj = (const float*)d_in[7];
    float* out = (float*)d_out;

    (void)in_sizes; (void)n_in; (void)out_size;

    cudaFuncSetAttribute(gemm_k, cudaFuncAttributeMaxDynamicSharedMemorySize,
                         GEMM_SMEM);
    gemm_k<<<M_DIM / GROWS, 128, GEMM_SMEM>>>(x, W_ih, b_ih, b_hh);
    // 4 elements per warp: T*B/4 warps, 8 warps (256 threads) per block
    scan_seg4_k<<<M_DIM / 4 / 8, 256>>>(reset, W_hh, W_proj, b_proj, out);
}

// round 16
// speedup vs baseline: 1.8764x; 1.2328x over previous
#include <cuda_runtime.h>
#include <cstdint>

#define T_DIM 2048
#define B_DIM 256
#define D_DIM 256
#define H_DIM 8
#define G_DIM 32
#define M_DIM (T_DIM * B_DIM)

// Scratch for x_gates (+ folded biases): [T*B][8 h-idx][4 gates i,f,g,o] fp32
__device__ float g_xg[(size_t)M_DIM * G_DIM];

// ---------------------------------------------------------------------------
// Packed f32x2 FMA (sm_103a): d = a*b + d  (two independent fp32 FMAs)
// ---------------------------------------------------------------------------
__device__ __forceinline__ void fma2(unsigned long long& d,
                                     unsigned long long a,
                                     unsigned long long b) {
    asm("fma.rn.f32x2 %0, %1, %2, %0;" : "+l"(d) : "l"(a), "l"(b));
}

__device__ __forceinline__ float ex2a(float x) {
    float y; asm("ex2.approx.ftz.f32 %0, %1;" : "=f"(y) : "f"(x)); return y;
}
__device__ __forceinline__ float rcpa(float x) {
    float y; asm("rcp.approx.ftz.f32 %0, %1;" : "=f"(y) : "f"(x)); return y;
}

__device__ __forceinline__ void cpa16(uint32_t s, const void* g) {
    asm volatile("cp.async.cg.shared.global [%0], [%1], 16;"
                 :: "r"(s), "l"(g));
}
#define CP_COMMIT() asm volatile("cp.async.commit_group;" ::: "memory")
#define CP_WAIT1()  asm volatile("cp.async.wait_group 1;" ::: "memory")

// Launch-parity shim so ncu (-s 5 -c 1) lands on the gemm: pattern
// [noop, gemm, scan, noop] has period 4; launch #5 = index 1 = gemm.
__global__ void noop_k() {}

// ---------------------------------------------------------------------------
// GEMM v4 (persistent + cp.async double-buffered K-halves):
//   x_gates[m, g] = sum_k x[m,k] * W_ih[g,k] + (b_ih[g] + b_hh[g])
// M = 524288, K = 256, N = 32.
// 148 CTAs (1/SM), 256 threads. W staged into smem ONCE per CTA (kills the
// 256 MB of redundant W restaging v1 did). Each CTA loops over 128-row
// tiles (stride 148); each tile's x arrives in two 64 KB K-halves through
// two smem buffers via cp.async, overlapped with compute of the other half.
// Inner loop = v1's exact 8-LDS + 16-FFMA2 per k-pair.
// Thread tile: rows {q, q+32, q+64, q+96} x gates {g0, g0+8, g0+16, g0+24}
// (q = tid>>3, g0 = tid&7). Row stride 132 floats (16B aligned for cp.async);
// a warp's 4 x-addrs are 132 floats apart -> banks {0,4,8,12}: conflict-free.
// Epilogue layout [row][h_idx][i,f,g,o] = one float4 per h-index for the scan.
// ---------------------------------------------------------------------------
#define TROWS 128
#define KHALF 128
#define SXH 132                              // x half-buffer row stride (floats)
#define XBUF_FLOATS (TROWS * SXH)            // 16896
#define GEMM_SMEM (2 * XBUF_FLOATS * 4 + 128 * 33 * 8)   // 168960 B
#define NTILES (M_DIM / TROWS)               // 4096
#define GEMM_CTAS 148

__global__ void __launch_bounds__(256, 1) gemm_k(
    const float* __restrict__ x, const float* __restrict__ W_ih,
    const float* __restrict__ b_ih, const float* __restrict__ b_hh)
{
    extern __shared__ float sm[];
    float* xs0 = sm;
    float* xs1 = sm + XBUF_FLOATS;
    unsigned long long* ws = (unsigned long long*)(sm + 2 * XBUF_FLOATS);
    const int tid = threadIdx.x;

    // Stage W once: ws[kp*33 + g] = W_ih[g][2kp..2kp+1] (k-pair packed)
    const float2* W2 = (const float2*)W_ih;
    for (int u = tid; u < 32 * 128; u += 256) {
        int g = u >> 7, kp = u & 127;
        float2 v = W2[(size_t)g * 128 + kp];
        ((float2*)ws)[kp * 33 + g] = v;
    }

    const int g0 = tid & 7;
    const int q  = tid >> 3;       // 0..31

    float bias[4];
#pragma unroll
    for (int j = 0; j < 4; j++) bias[j] = b_ih[g0 + 8 * j] + b_hh[g0 + 8 * j];

    const uint32_t s0 = (uint32_t)__cvta_generic_to_shared(xs0);
    const uint32_t s1 = (uint32_t)__cvta_generic_to_shared(xs1);

    // ---- stage one K-half of a tile into a buffer (cp.async, 16B) ----
    auto load_half = [&](uint32_t sbuf, int t, int h) {
        const float* src = x + (size_t)t * TROWS * D_DIM + h * KHALF;
        for (int u = tid; u < TROWS * 32; u += 256) {   // 32 float4 per row
            int r = u >> 5, k4 = u & 31;
            cpa16(sbuf + (uint32_t)(r * SXH + k4 * 4) * 4,
                  src + (size_t)r * D_DIM + k4 * 4);
        }
    };

    // ---- compute one K-half from a buffer into acc ----
    auto compute_half = [&](const float* buf, int h,
                            unsigned long long (&acc)[4][4]) {
        const unsigned long long* xr0 =
            (const unsigned long long*)(buf + (q + 0) * SXH);
        const unsigned long long* xr1 =
            (const unsigned long long*)(buf + (q + 32) * SXH);
        const unsigned long long* xr2 =
            (const unsigned long long*)(buf + (q + 64) * SXH);
        const unsigned long long* xr3 =
            (const unsigned long long*)(buf + (q + 96) * SXH);
        const unsigned long long* wb = ws + (size_t)h * 64 * 33;
#pragma unroll 4
        for (int kp = 0; kp < 64; kp++) {
            unsigned long long w0 = wb[kp * 33 + g0 + 0];
            unsigned long long w1 = wb[kp * 33 + g0 + 8];
            unsigned long long w2 = wb[kp * 33 + g0 + 16];
            unsigned long long w3 = wb[kp * 33 + g0 + 24];
            unsigned long long xa = xr0[kp], xb = xr1[kp];
            unsigned long long xc = xr2[kp], xd = xr3[kp];
            fma2(acc[0][0], xa, w0); fma2(acc[0][1], xa, w1);
            fma2(acc[0][2], xa, w2); fma2(acc[0][3], xa, w3);
            fma2(acc[1][0], xb, w0); fma2(acc[1][1], xb, w1);
            fma2(acc[1][2], xb, w2); fma2(acc[1][3], xb, w3);
            fma2(acc[2][0], xc, w0); fma2(acc[2][1], xc, w1);
            fma2(acc[2][2], xc, w2); fma2(acc[2][3], xc, w3);
            fma2(acc[3][0], xd, w0); fma2(acc[3][1], xd, w1);
            fma2(acc[3][2], xd, w2); fma2(acc[3][3], xd, w3);
        }
    };

    // ---- pipelined tile loop ----
    // groups: preload A(g1); per iter: B(g_k); wait1 -> prev buf ready.
    int t = blockIdx.x;
    load_half(s0, t, 0);
    CP_COMMIT();

    for (; t < NTILES; t += GEMM_CTAS) {
        unsigned long long acc[4][4];
#pragma unroll
        for (int i = 0; i < 4; i++)
#pragma unroll
            for (int j = 0; j < 4; j++) acc[i][j] = 0ULL;

        load_half(s1, t, 1);
        CP_COMMIT();
        CP_WAIT1();               // half0 (xs0) arrived
        __syncthreads();
        compute_half(xs0, 0, acc);
        __syncthreads();          // all reads of xs0 done before overwrite

        const int nt = t + GEMM_CTAS;
        if (nt < NTILES) load_half(s0, nt, 0);
        CP_COMMIT();
        CP_WAIT1();               // half1 (xs1) arrived
        __syncthreads();
        compute_half(xs1, 1, acc);

        // epilogue: [row][h_idx q... wait: h_idx = g0][i,f,g,o]
#pragma unroll
        for (int i = 0; i < 4; i++) {
            const size_t row = (size_t)t * TROWS + q + 32 * i;
            float4 v;
            v.x = __uint_as_float((unsigned)acc[i][0]) +
                  __uint_as_float((unsigned)(acc[i][0] >> 32)) + bias[0];
            v.y = __uint_as_float((unsigned)acc[i][1]) +
                  __uint_as_float((unsigned)(acc[i][1] >> 32)) + bias[1];
            v.z = __uint_as_float((unsigned)acc[i][2]) +
                  __uint_as_float((unsigned)(acc[i][2] >> 32)) + bias[2];
            v.w = __uint_as_float((unsigned)acc[i][3]) +
                  __uint_as_float((unsigned)(acc[i][3] >> 32)) + bias[3];
            *(float4*)&g_xg[row * G_DIM + g0 * 4] = v;
        }
        __syncthreads();          // all reads of xs1 done before next iter
    }
}

// ---------------------------------------------------------------------------
// Segment-parallel LSTM scan v2 (unchanged from R14 — 119.7us, known correct).
// 8 lanes per (t,b) element, 4 elements/warp. Lane j owns h_j, computes its
// 4 gates from registers; only an 8-wide h broadcast per step.
// ---------------------------------------------------------------------------
__global__ void __launch_bounds__(256) scan_seg4_k(
    const int* __restrict__ reset,
    const float* __restrict__ W_hh, const float* __restrict__ W_proj,
    const float* __restrict__ b_proj, float* __restrict__ out)
{
    const int lane = threadIdx.x & 31;
    const int wid = (blockIdx.x * blockDim.x + threadIdx.x) >> 5;
    const int grp = lane >> 3;
    const int p   = lane & 7;
    const int gid = wid * 4 + grp;
    const int t0 = gid >> 8;
    const int b  = gid & 255;

    bool alive = (t0 == 0) || (reset[(size_t)t0 * B_DIM + b] != 0);
    if (__ballot_sync(0xffffffffu, alive) == 0) return;

    float wi[8], wf[8], wg[8], wo[8], wp[8];
    const float4* W4 = (const float4*)W_hh;
    {
        float4 a, q;
        a = W4[(p +  0) * 2]; q = W4[(p +  0) * 2 + 1];
        wi[0]=a.x; wi[1]=a.y; wi[2]=a.z; wi[3]=a.w;
        wi[4]=q.x; wi[5]=q.y; wi[6]=q.z; wi[7]=q.w;
        a = W4[(p +  8) * 2]; q = W4[(p +  8) * 2 + 1];
        wf[0]=a.x; wf[1]=a.y; wf[2]=a.z; wf[3]=a.w;
        wf[4]=q.x; wf[5]=q.y; wf[6]=q.z; wf[7]=q.w;
        a = W4[(p + 16) * 2]; q = W4[(p + 16) * 2 + 1];
        wg[0]=a.x; wg[1]=a.y; wg[2]=a.z; wg[3]=a.w;
        wg[4]=q.x; wg[5]=q.y; wg[6]=q.z; wg[7]=q.w;
        a = W4[(p + 24) * 2]; q = W4[(p + 24) * 2 + 1];
        wo[0]=a.x; wo[1]=a.y; wo[2]=a.z; wo[3]=a.w;
        wo[4]=q.x; wo[5]=q.y; wo[6]=q.z; wo[7]=q.w;
    }
#pragma unroll
    for (int j = 0; j < 8; j++) wp[j] = W_proj[j];
    const float bp = b_proj[0];

    float h[8];
#pragma unroll
    for (int j = 0; j < 8; j++) h[j] = 0.f;
    float c = 0.f;

    const float4* xg4 = (const float4*)g_xg;
    float4 xcur = xg4[((size_t)t0 * B_DIM + b) * 8 + p];

    int base = t0;
    while (true) {
        const int idx = base + p;
        const int rw = (alive && idx < T_DIM)
                     ? reset[(size_t)idx * B_DIM + b] : 1;
        unsigned bal = __ballot_sync(0xffffffffu, rw != 0);
        unsigned m8 = (bal >> (grp * 8)) & 0xffu;
        if (base == t0) m8 &= 0xfeu;
        int cnt = m8 ? (__ffs((int)m8) - 1) : 8;
        if (!alive) cnt = 0;

        for (int i = 0; i < 8; i++) {
            const bool stepping = alive && (i < cnt);
            if (__ballot_sync(0xffffffffu, stepping) == 0u) break;
            const int tt = base + i;
            float4 xnext = xcur;
            if (stepping && tt + 1 < T_DIM)
                xnext = xg4[((size_t)(tt + 1) * B_DIM + b) * 8 + p];

            float ig = xcur.x, fg = xcur.y, gg = xcur.z, og = xcur.w;
#pragma unroll
            for (int k = 0; k < 8; k++) {
                ig = fmaf(wi[k], h[k], ig);
                fg = fmaf(wf[k], h[k], fg);
                gg = fmaf(wg[k], h[k], gg);
                og = fmaf(wo[k], h[k], og);
            }
            const float iv = rcpa(1.f + ex2a(-1.4426950408889634f * ig));
            const float fv = rcpa(1.f + ex2a(-1.4426950408889634f * fg));
            const float gv = fmaf(2.f,
                rcpa(1.f + ex2a(-2.8853900817779268f * gg)), -1.f);
            const float ov = rcpa(1.f + ex2a(-1.4426950408889634f * og));
            const float cn = fmaf(fv, c, iv * gv);
            const float tc = fmaf(2.f,
                rcpa(1.f + ex2a(-2.8853900817779268f * cn)), -1.f);
            const float hj = ov * tc;
            if (stepping) c = cn;
            const float hsrc = stepping ? hj : h[p];
#pragma unroll
            for (int k = 0; k < 8; k++)
                h[k] = __shfl_sync(0xffffffffu, hsrc, (lane & 24) + k);
            float pv = bp;
#pragma unroll
            for (int k = 0; k < 8; k++) pv = fmaf(h[k], wp[k], pv);
            if (stepping && p == 0) out[(size_t)tt * B_DIM + b] = pv;
            xcur = xnext;
        }

        alive = alive && (cnt == 8);
        if (__ballot_sync(0xffffffffu, alive) == 0u) return;
        base += 8;
    }
}

// ---------------------------------------------------------------------------
extern "C" void kernel_launch(void* const* d_in, const int* in_sizes, int n_in,
                              void* d_out, int out_size)
{
    const float* x      = (const float*)d_in[0];
    const int*   reset  = (const int*)d_in[1];
    const float* W_ih   = (const float*)d_in[2];
    const float* W_hh   = (const float*)d_in[3];
    const float* b_ih   = (const float*)d_in[4];
    const float* b_hh   = (const float*)d_in[5];
    const float* W_proj = (const float*)d_in[6];
    const float* b_proj = (const float*)d_in[7];
    float* out = (float*)d_out;

    (void)in_sizes; (void)n_in; (void)out_size;

    cudaFuncSetAttribute(gemm_k, cudaFuncAttributeMaxDynamicSharedMemorySize,
                         GEMM_SMEM);
    noop_k<<<1, 32>>>();
    gemm_k<<<GEMM_CTAS, 256, GEMM_SMEM>>>(x, W_ih, b_ih, b_hh);
    scan_seg4_k<<<M_DIM / 4 / 8, 256>>>(reset, W_hh, W_proj, b_proj, out);
    noop_k<<<1, 32>>>();
}